// round 16
// baseline (speedup 1.0000x reference)
#include <cuda_runtime.h>
#include <cuda_bf16.h>
#include <cstdint>

#define NN 50000
#define NE 600000
#define DIM 128
#define NR 8
#define NB 8
#define NG 256
#define KW 384       // W2 per relation: [Whi ; Whi ; Wlo]
#define WSZ (NR * DIM * KW)
#define NN8 (NN * NR)
#define NBLK ((NN8 + 255) / 256)

// ---------------- static device scratch ----------------
__device__ __nv_bfloat16 g_Y2[(size_t)NN8 * 256];            // aggregated split input, 204.8MB
__device__ __nv_bfloat16 g_W2[3 * WSZ];                      // split weights, all 3 layers
__device__ float g_hA[(size_t)NN * DIM];
__device__ float g_hB[(size_t)NN * DIM];
__device__ float g_gate[NN];
__device__ float g_gmax[NG];
__device__ float g_gsum[NG];
__device__ float g_read[NG * DIM];
// CSR keyed (etype*NN + dst)
__device__ int g_cursor2[NN8];
__device__ int g_rowptr2[NN8 + 1];
__device__ int g_blktot[NBLK];
__device__ int g_blkbase[NBLK];
__device__ int g_eidx2[NE];                                  // src only

// ---------------- PTX helpers (Ampere-class ISA only) ----------------
__device__ __forceinline__ uint32_t smem_u32(const void* p) {
    uint32_t a;
    asm("{ .reg .u64 t; cvta.to.shared.u64 t, %1; cvt.u32.u64 %0, t; }" : "=r"(a) : "l"(p));
    return a;
}
#define CP_ASYNC16(dst, src) \
    asm volatile("cp.async.cg.shared.global [%0], [%1], 16;" :: "r"(dst), "l"(src))
#define CP_COMMIT() asm volatile("cp.async.commit_group;" ::: "memory")
#define CP_WAIT(n)  asm volatile("cp.async.wait_group %0;" :: "n"(n) : "memory")

#define LDMX4(f, addr) asm volatile( \
    "ldmatrix.sync.aligned.m8n8.x4.shared.b16 {%0,%1,%2,%3}, [%4];" \
    : "=r"((f)[0]), "=r"((f)[1]), "=r"((f)[2]), "=r"((f)[3]) : "r"(addr))

#define MMA_BF16(d, a, b0, b1) asm volatile( \
    "mma.sync.aligned.m16n8k16.row.col.f32.bf16.bf16.f32 " \
    "{%0,%1,%2,%3}, {%4,%5,%6,%7}, {%8,%9}, {%0,%1,%2,%3};" \
    : "+f"((d)[0]), "+f"((d)[1]), "+f"((d)[2]), "+f"((d)[3]) \
    : "r"((a)[0]), "r"((a)[1]), "r"((a)[2]), "r"((a)[3]), "r"(b0), "r"(b1))

// ---------------- CSR build: key = etype*NN + dst (R13-proven) ----------------
__global__ void k_hist0() {
    int i = blockIdx.x * 256 + threadIdx.x;
    if (i < NN8) g_cursor2[i] = 0;
}
__global__ void k_hist2(const int* __restrict__ dst, const int* __restrict__ et) {
    int e = blockIdx.x * 256 + threadIdx.x;
    if (e < NE) atomicAdd(&g_cursor2[__ldg(et + e) * NN + __ldg(dst + e)], 1);
}
__global__ void k_blksum() {
    __shared__ int sh[8];
    int t = threadIdx.x, lane = t & 31, w = t >> 5;
    int key = blockIdx.x * 256 + t;
    int v = (key < NN8) ? g_cursor2[key] : 0;
#pragma unroll
    for (int o = 16; o; o >>= 1) v += __shfl_xor_sync(0xffffffffu, v, o);
    if (lane == 0) sh[w] = v;
    __syncthreads();
    if (t == 0) {
        int s = 0;
#pragma unroll
        for (int j = 0; j < 8; j++) s += sh[j];
        g_blktot[blockIdx.x] = s;
    }
}
__global__ __launch_bounds__(1024) void k_blkscan() {
    __shared__ int wsum[32];
    __shared__ int s_carry;
    const int tid = threadIdx.x, lane = tid & 31, wid = tid >> 5;
    if (tid == 0) s_carry = 0;
    __syncthreads();
    for (int base = 0; base < NBLK; base += 1024) {
        int i = base + tid;
        int v = (i < NBLK) ? g_blktot[i] : 0;
        int x = v;
#pragma unroll
        for (int o = 1; o < 32; o <<= 1) {
            int y = __shfl_up_sync(0xffffffffu, x, o);
            if (lane >= o) x += y;
        }
        if (lane == 31) wsum[wid] = x;
        __syncthreads();
        if (wid == 0) {
            int w = (lane < 32) ? wsum[lane] : 0;
#pragma unroll
            for (int o = 1; o < 32; o <<= 1) {
                int y = __shfl_up_sync(0xffffffffu, w, o);
                if (lane >= o) w += y;
            }
            wsum[lane] = w;
        }
        __syncthreads();
        int incl = x + (wid > 0 ? wsum[wid - 1] : 0) + s_carry;
        if (i < NBLK) g_blkbase[i] = incl - v;
        __syncthreads();
        if (tid == 1023) s_carry = incl;
        __syncthreads();
    }
}
__global__ void k_rowptr() {
    __shared__ int wsum[8];
    int t = threadIdx.x, lane = t & 31, w = t >> 5;
    int key = blockIdx.x * 256 + t;
    int v = (key < NN8) ? g_cursor2[key] : 0;
    int x = v;
#pragma unroll
    for (int o = 1; o < 32; o <<= 1) {
        int y = __shfl_up_sync(0xffffffffu, x, o);
        if (lane >= o) x += y;
    }
    if (lane == 31) wsum[w] = x;
    __syncthreads();
    if (t == 0) {
        int run = 0;
#pragma unroll
        for (int j = 0; j < 8; j++) { int c = wsum[j]; wsum[j] = run; run += c; }
    }
    __syncthreads();
    int excl = x - v + wsum[w] + g_blkbase[blockIdx.x];
    if (key < NN8) { g_rowptr2[key] = excl; g_cursor2[key] = excl; }
    if (key == NN8 - 1) g_rowptr2[NN8] = excl + v;
}
__global__ void k_fill2(const int* __restrict__ src, const int* __restrict__ dst,
                        const int* __restrict__ et) {
    int e = blockIdx.x * 256 + threadIdx.x;
    if (e >= NE) return;
    int key = __ldg(et + e) * NN + __ldg(dst + e);
    int pos = atomicAdd(&g_cursor2[key], 1);
    g_eidx2[pos] = __ldg(src + e);
}

// ---------------- split weights: all 3 layers in one launch ----------------
__global__ void k_splitw3(const float* __restrict__ b1, const float* __restrict__ c1,
                          const float* __restrict__ b2, const float* __restrict__ c2,
                          const float* __restrict__ b3, const float* __restrict__ c3) {
    int layer = blockIdx.z;
    const float* bases = (layer == 0) ? b1 : (layer == 1 ? b2 : b3);
    const float* comp  = (layer == 0) ? c1 : (layer == 1 ? c2 : c3);
    int r = blockIdx.y;
    int t = blockIdx.x * 256 + threadIdx.x;
    if (t >= DIM * DIM) return;
    int k = t >> 7, n = t & 127;
    float s = 0.f;
#pragma unroll
    for (int b = 0; b < NB; b++)
        s = fmaf(comp[r * NB + b], bases[((size_t)b * DIM + k) * DIM + n], s);
    __nv_bfloat16 hi = __float2bfloat16(s);
    __nv_bfloat16 lo = __float2bfloat16(s - __bfloat162float(hi));
    __nv_bfloat16* w = g_W2 + (size_t)layer * WSZ + ((size_t)r * DIM + n) * KW;
    w[k] = hi; w[128 + k] = hi; w[256 + k] = lo;
}

// ---------------- aggregate: Y2[n,r] = split( sum_{e in CSR[r,n]} relu?(x[src]) ) ----------------
// warp per (n,r); 400K warps; x is 25.6MB -> L2-resident random reads
__global__ void k_aggregate(const float* __restrict__ xf, int xsel, int relu_in) {
    const float* x = (xsel == 0) ? xf : (xsel == 1 ? g_hA : g_hB);
    int w = blockIdx.x * 8 + (threadIdx.x >> 5);
    if (w >= NN8) return;
    int lane = threadIdx.x & 31;
    int n = w >> 3, r = w & 7;
    int key = r * NN + n;
    int beg = __ldg(&g_rowptr2[key]), end = __ldg(&g_rowptr2[key + 1]);
    const float4* x4 = (const float4*)x;
    float4 a0 = make_float4(0.f, 0.f, 0.f, 0.f);
    float4 a1 = make_float4(0.f, 0.f, 0.f, 0.f);
    int e = beg;
    for (; e + 1 < end; e += 2) {
        int p0 = __ldg(&g_eidx2[e]), p1 = __ldg(&g_eidx2[e + 1]);
        float4 v0 = x4[(size_t)p0 * 32 + lane];
        float4 v1 = x4[(size_t)p1 * 32 + lane];
        if (relu_in) {
            v0.x = fmaxf(v0.x, 0.f); v0.y = fmaxf(v0.y, 0.f);
            v0.z = fmaxf(v0.z, 0.f); v0.w = fmaxf(v0.w, 0.f);
            v1.x = fmaxf(v1.x, 0.f); v1.y = fmaxf(v1.y, 0.f);
            v1.z = fmaxf(v1.z, 0.f); v1.w = fmaxf(v1.w, 0.f);
        }
        a0.x += v0.x; a0.y += v0.y; a0.z += v0.z; a0.w += v0.w;
        a1.x += v1.x; a1.y += v1.y; a1.z += v1.z; a1.w += v1.w;
    }
    if (e < end) {
        int p = __ldg(&g_eidx2[e]);
        float4 v = x4[(size_t)p * 32 + lane];
        if (relu_in) {
            v.x = fmaxf(v.x, 0.f); v.y = fmaxf(v.y, 0.f);
            v.z = fmaxf(v.z, 0.f); v.w = fmaxf(v.w, 0.f);
        }
        a0.x += v.x; a0.y += v.y; a0.z += v.z; a0.w += v.w;
    }
    a0.x += a1.x; a0.y += a1.y; a0.z += a1.z; a0.w += a1.w;
    float f[4] = {a0.x, a0.y, a0.z, a0.w};
    __nv_bfloat16 h[4], l[4];
#pragma unroll
    for (int i = 0; i < 4; i++) {
        h[i] = __float2bfloat16(f[i]);
        l[i] = __float2bfloat16(f[i] - __bfloat162float(h[i]));
    }
    __nv_bfloat16* y = g_Y2 + ((size_t)n * NR + r) * 256 + lane * 4;
    *(uint2*)(y)       = *(uint2*)h;
    *(uint2*)(y + 128) = *(uint2*)l;
}

// ---------------- out[n,:] = bias (vectorized) ----------------
__global__ void k_init(const float* __restrict__ bias, int whichOut) {
    float4* out = (float4*)((whichOut == 1) ? g_hA : g_hB);
    size_t idx = (size_t)blockIdx.x * blockDim.x + threadIdx.x;   // NN*32
    if (idx < (size_t)NN * 32)
        out[idx] = ((const float4*)bias)[idx & 31];
}

// ---------------- HMMA GEMM split-K by relation: out[n] += Y2[n,r] @ W_r ----------------
// grid = (NR, 391); R15 GEMM structure; epilogue = red.global.add.v2.f32
#define MAT_BYTES   (128 * 72 * 2)
#define STAGE_FULL  (2 * MAT_BYTES)
__global__ __launch_bounds__(256, 2) void k_gemm_mma(int layer, int outsel) {
    constexpr int SP = 72;
    extern __shared__ __align__(16) char dynsmem[];

    const int tid = threadIdx.x;
    const int wid = tid >> 5, lane = tid & 31;
    const int r = blockIdx.x;
    const int m0 = blockIdx.y * 128;
    const int wm = (wid & 3) * 32;
    const int wn = (wid >> 2) * 64;

    float* outp = (outsel == 1) ? g_hA : g_hB;
    const __nv_bfloat16* __restrict__ Ag = g_Y2;
    const __nv_bfloat16* __restrict__ Bg = g_W2 + (size_t)layer * WSZ + (size_t)r * DIM * KW;

    const int a_off[6] = {0, 64, 128, 192, 0, 64};        // hi hi lo lo hi hi

    float acc[2][8][4];
#pragma unroll
    for (int mi = 0; mi < 2; mi++)
#pragma unroll
        for (int ni = 0; ni < 8; ni++)
#pragma unroll
            for (int q = 0; q < 4; q++) acc[mi][ni][q] = 0.f;

    const uint32_t smem_base = smem_u32(dynsmem);
    const int lrow = (lane & 15);
    const int lcol = (lane & 16) ? 8 : 0;

    auto stage = [&](int kc, int buf) {
        uint32_t sA_b = smem_base + buf * STAGE_FULL;
        uint32_t sB_b = sA_b + MAT_BYTES;
#pragma unroll
        for (int i = 0; i < 4; i++) {
            int id = tid + i * 256;
            int row = id >> 3, seg = id & 7;
            int gr = m0 + row; if (gr >= NN) gr = NN - 1;
            CP_ASYNC16(sA_b + (row * SP + seg * 8) * 2,
                       Ag + ((size_t)gr * NR + r) * 256 + a_off[kc] + seg * 8);
            CP_ASYNC16(sB_b + (row * SP + seg * 8) * 2,
                       Bg + (size_t)row * KW + kc * 64 + seg * 8);
        }
        CP_COMMIT();
    };

    stage(0, 0);
    stage(1, 1);

    for (int kc = 0; kc < 6; kc++) {
        const int buf = kc % 3;
        if (kc < 5) CP_WAIT(1); else CP_WAIT(0);
        __syncthreads();
        if (kc + 2 < 6) stage(kc + 2, (kc + 2) % 3);

        const uint32_t sA_b = smem_base + buf * STAGE_FULL;
        const uint32_t sB_b = sA_b + MAT_BYTES;
#pragma unroll
        for (int ks = 0; ks < 4; ks++) {
            const int k0 = ks * 16;
            uint32_t aF[2][4], bF[4][4];
#pragma unroll
            for (int mi = 0; mi < 2; mi++)
                LDMX4(aF[mi], sA_b + ((wm + mi * 16 + lrow) * SP + k0 + lcol) * 2);
#pragma unroll
            for (int g = 0; g < 4; g++)
                LDMX4(bF[g], sB_b + ((wn + g * 16 + lrow) * SP + k0 + lcol) * 2);
#pragma unroll
            for (int mi = 0; mi < 2; mi++)
#pragma unroll
                for (int ni = 0; ni < 8; ni++) {
                    uint32_t b0 = bF[ni >> 1][(ni & 1)];
                    uint32_t b1 = bF[ni >> 1][(ni & 1) + 2];
                    MMA_BF16(acc[mi][ni], aF[mi], b0, b1);
                }
        }
    }

    // epilogue: atomically add relation-partial into out (L2-resident 25.6MB)
#pragma unroll
    for (int mi = 0; mi < 2; mi++) {
        int row0 = m0 + wm + mi * 16 + (lane >> 2);
#pragma unroll
        for (int half = 0; half < 2; half++) {
            int gr = row0 + half * 8;
            if (gr < NN) {
                float* base = outp + (size_t)gr * DIM + wn + (lane & 3) * 2;
#pragma unroll
                for (int ni = 0; ni < 8; ni++)
                    asm volatile("red.global.add.v2.f32 [%0], {%1,%2};"
                                 :: "l"(base + ni * 8),
                                    "f"(acc[mi][ni][half * 2]),
                                    "f"(acc[mi][ni][half * 2 + 1]) : "memory");
            }
        }
    }
}

// ---------------- pooling ----------------
__global__ void k_poolinit() {
    int idx = blockIdx.x * blockDim.x + threadIdx.x;
    if (idx < NG) { g_gmax[idx] = -__int_as_float(0x7f800000); g_gsum[idx] = 0.f; }
    if (idx < NG * DIM) g_read[idx] = 0.f;
}

__global__ void k_gate(const float* __restrict__ gw, const float* __restrict__ gb,
                       const int* __restrict__ n2g) {
    int n = blockIdx.x * 8 + (threadIdx.x >> 5);
    if (n >= NN) return;
    int lane = threadIdx.x & 31;
    float4 hv = ((const float4*)(g_hA + (size_t)n * DIM))[lane];
    float4 wv = ((const float4*)gw)[lane];
    float s = hv.x * wv.x + hv.y * wv.y + hv.z * wv.z + hv.w * wv.w;
#pragma unroll
    for (int o = 16; o; o >>= 1) s += __shfl_xor_sync(0xffffffffu, s, o);
    if (lane == 0) {
        s += gb[0];
        g_gate[n] = s;
        int g = n2g[n];
        int* ia = (int*)&g_gmax[g];
        int old = *ia;
        while (__int_as_float(old) < s) {
            int prev = atomicCAS(ia, old, __float_as_int(s));
            if (prev == old) break;
            old = prev;
        }
    }
}

__global__ void k_expsum(const int* __restrict__ n2g) {
    int n = blockIdx.x * blockDim.x + threadIdx.x;
    if (n >= NN) return;
    int g = n2g[n];
    float e = expf(g_gate[n] - g_gmax[g]);
    g_gate[n] = e;
    atomicAdd(&g_gsum[g], e);
}

__global__ void k_readout(const int* __restrict__ n2g) {
    int n = blockIdx.x * 8 + (threadIdx.x >> 5);
    if (n >= NN) return;
    int lane = threadIdx.x & 31;
    int g = n2g[n];
    float w = g_gate[n] / g_gsum[g];
    float4 hv = ((const float4*)(g_hA + (size_t)n * DIM))[lane];
    float* o = g_read + g * DIM + lane * 4;
    asm volatile("red.global.add.v4.f32 [%0], {%1,%2,%3,%4};"
                 :: "l"(o), "f"(hv.x * w), "f"(hv.y * w), "f"(hv.z * w), "f"(hv.w * w)
                 : "memory");
}

// ---------------- MLP head ----------------
__global__ void k_mlp(const float* __restrict__ fc1_w, const float* __restrict__ fc1_b,
                      const float* __restrict__ fc2_w, const float* __restrict__ fc2_b,
                      const float* __restrict__ fc3_w, const float* __restrict__ fc3_b,
                      float* __restrict__ out) {
    int g = blockIdx.x;
    int t = threadIdx.x;
    __shared__ float r[DIM];
    __shared__ float z1[100];
    __shared__ float z2[64];
    r[t] = g_read[g * DIM + t];
    __syncthreads();
    if (t < 100) {
        float s = fc1_b[t];
        for (int i = 0; i < DIM; i++) s = fmaf(r[i], fc1_w[i * 100 + t], s);
        z1[t] = fmaxf(s, 0.f);
    }
    __syncthreads();
    if (t < 64) {
        float s = fc2_b[t];
        for (int i = 0; i < 100; i++) s = fmaf(z1[i], fc2_w[i * 64 + t], s);
        z2[t] = fmaxf(s, 0.f);
    }
    __syncthreads();
    if (t == 0) {
        float s = fc3_b[0];
        for (int i = 0; i < 64; i++) s = fmaf(z2[i], fc3_w[i], s);
        out[g] = 1.f / (1.f + expf(-s));
    }
}

// ---------------- host launcher ----------------
extern "C" void kernel_launch(void* const* d_in, const int* in_sizes, int n_in,
                              void* d_out, int out_size) {
    const float *features, *bases1, *comp1, *bias1, *bases2, *comp2, *bias2;
    const float *bases3, *comp3, *bias3, *gate_w, *gate_b;
    const float *fc1_w, *fc1_b, *fc2_w, *fc2_b, *fc3_w, *fc3_b;
    const int *src, *dst, *etype, *n2g;

    if (in_sizes[1] == NE) {
        features = (const float*)d_in[0];
        src      = (const int*)d_in[1];
        dst      = (const int*)d_in[2];
        etype    = (const int*)d_in[3];
        n2g      = (const int*)d_in[4];
        bases1 = (const float*)d_in[5];  comp1 = (const float*)d_in[6];  bias1 = (const float*)d_in[7];
        bases2 = (const float*)d_in[8];  comp2 = (const float*)d_in[9];  bias2 = (const float*)d_in[10];
        bases3 = (const float*)d_in[11]; comp3 = (const float*)d_in[12]; bias3 = (const float*)d_in[13];
        gate_w = (const float*)d_in[14]; gate_b = (const float*)d_in[15];
        fc1_w = (const float*)d_in[16]; fc1_b = (const float*)d_in[17];
        fc2_w = (const float*)d_in[18]; fc2_b = (const float*)d_in[19];
        fc3_w = (const float*)d_in[20]; fc3_b = (const float*)d_in[21];
    } else {
        features = (const float*)d_in[0];
        bases1 = (const float*)d_in[1];  comp1 = (const float*)d_in[2];  bias1 = (const float*)d_in[3];
        bases2 = (const float*)d_in[4];  comp2 = (const float*)d_in[5];  bias2 = (const float*)d_in[6];
        bases3 = (const float*)d_in[7];  comp3 = (const float*)d_in[8];  bias3 = (const float*)d_in[9];
        gate_w = (const float*)d_in[10]; gate_b = (const float*)d_in[11];
        fc1_w = (const float*)d_in[12]; fc1_b = (const float*)d_in[13];
        fc2_w = (const float*)d_in[14]; fc2_b = (const float*)d_in[15];
        fc3_w = (const float*)d_in[16]; fc3_b = (const float*)d_in[17];
        src   = (const int*)d_in[18];
        dst   = (const int*)d_in[19];
        etype = (const int*)d_in[20];
        n2g   = (const int*)d_in[21];
    }
    float* out = (float*)d_out;

    const dim3 gemm_grid(NR, (NN + 127) / 128);          // 8 x 391
    const dim3 splitw_grid(64, NR, 3);
    const int agg_blocks = NN8 / 8;                      // 50000
    const int init_blocks = (NN * 32 + 255) / 256;       // 6250
    const int node_warp_blocks = NN / 8;                 // 6250
    const int edge_blocks = (NE + 255) / 256;            // 2344
    const int gemm_smem = 3 * STAGE_FULL;                // 110592 B

    static int smem_set = 0;
    if (!smem_set) {
        cudaFuncSetAttribute(k_gemm_mma, cudaFuncAttributeMaxDynamicSharedMemorySize, gemm_smem);
        smem_set = 1;
    }

    // ---- CSR keyed (etype, dst)
    k_hist0<<<NBLK, 256>>>();
    k_hist2<<<edge_blocks, 256>>>(dst, etype);
    k_blksum<<<NBLK, 256>>>();
    k_blkscan<<<1, 1024>>>();
    k_rowptr<<<NBLK, 256>>>();
    k_fill2<<<edge_blocks, 256>>>(src, dst, etype);
    k_splitw3<<<splitw_grid, 256>>>(bases1, comp1, bases2, comp2, bases3, comp3);

    // ---- layer 1: features -> g_hA
    k_aggregate<<<agg_blocks, 256>>>(features, 0, 0);
    k_init<<<init_blocks, 256>>>(bias1, 1);
    k_gemm_mma<<<gemm_grid, 256, gemm_smem>>>(0, 1);
    // ---- layer 2: relu(g_hA) -> g_hB
    k_aggregate<<<agg_blocks, 256>>>(features, 1, 1);
    k_init<<<init_blocks, 256>>>(bias2, 2);
    k_gemm_mma<<<gemm_grid, 256, gemm_smem>>>(1, 2);
    // ---- layer 3: relu(g_hB) -> g_hA
    k_aggregate<<<agg_blocks, 256>>>(features, 2, 1);
    k_init<<<init_blocks, 256>>>(bias3, 1);
    k_gemm_mma<<<gemm_grid, 256, gemm_smem>>>(2, 1);

    // ---- attention pooling on g_hA
    k_poolinit<<<(NG * DIM + 255) / 256, 256>>>();
    k_gate<<<node_warp_blocks, 256>>>(gate_w, gate_b, n2g);
    k_expsum<<<(NN + 255) / 256, 256>>>(n2g);
    k_readout<<<node_warp_blocks, 256>>>(n2g);
    // ---- MLP head
    k_mlp<<<NG, DIM>>>(fc1_w, fc1_b, fc2_w, fc2_b, fc3_w, fc3_b, out);
}